// round 10
// baseline (speedup 1.0000x reference)
#include <cuda_runtime.h>
#include <cuda_bf16.h>
#include <cstdint>

// Problem constants
#define Bb   8
#define Cch  128
#define Nn   2304      // 48*48
#define REDr 16
#define BM   128       // query tile rows per CTA
#define BN   64        // key tile per iteration
#define NTIL (Nn / BN) // 36
#define QK_STRIDE 132  // fp32 qkv-projection smem stride

// attn smem (uint32 word offsets); bf16 pairs packed in uint32.
// K rows [key][c2]: 64 data words + 4 pad = 68 (KSU). Plane = 64*68 = 4352.
// V rows [chan][key2]: 32 data words + 4 pad = 36 (VSU). Plane = 128*36 = 4608.
#define KSU  68
#define VSU  36
#define PSU  36
#define KPLANE (64 * KSU)     // 4352
#define VPLANE (128 * VSU)    // 4608
#define KBUF   (2 * KPLANE)   // hi+lo = 8704
#define VBUF   (2 * VPLANE)   // 9216
#define U_K0   0
#define U_V0   (2 * KBUF)             // 17408  (two K buffers first)
#define U_PS   (U_V0 + 2 * VBUF)      // 35840
#define ATTN_WORDS (U_PS + 128 * PSU) // 40448
#define ATTN_SMEM  (ATTN_WORDS * 4)   // 161792 B

// Scratch: preconverted bf16 hi/lo planes (packed pairs in uint32)
__device__ uint32_t g_qhi[Bb * Nn * 64];   // [b][n][c2]
__device__ uint32_t g_qlo[Bb * Nn * 64];
__device__ uint32_t g_khi[Bb * Nn * 64];   // [b][n][c2]
__device__ uint32_t g_klo[Bb * Nn * 64];
__device__ uint32_t g_vhi[Bb * Cch * (Nn / 2)];  // [b][c][n2]
__device__ uint32_t g_vlo[Bb * Cch * (Nn / 2)];
__device__ float g_mean[Bb * Cch];
__device__ float g_y[Bb * Cch];

__device__ __forceinline__ uint32_t smem_u32(const void* p) {
    uint32_t a;
    asm("{ .reg .u64 t; cvta.to.shared.u64 t, %1; cvt.u32.u64 %0, t; }" : "=r"(a) : "l"(p));
    return a;
}
// pack two floats to bf16x2 (rn): low half = first arg
__device__ __forceinline__ uint32_t pack_bf16(float lo, float hi) {
    uint32_t r;
    asm("cvt.rn.bf16x2.f32 %0, %1, %2;" : "=r"(r) : "f"(hi), "f"(lo));
    return r;
}
__device__ __forceinline__ float rb16(float a) {
    return __bfloat162float(__float2bfloat16(a));
}
#define CP_ASYNC16(dst_u32, src_ptr) \
    asm volatile("cp.async.cg.shared.global [%0], [%1], 16;" :: "r"(dst_u32), "l"(src_ptr))
#define CP_COMMIT() asm volatile("cp.async.commit_group;" ::: "memory")
#define CP_WAIT1()  asm volatile("cp.async.wait_group 1;" ::: "memory")
#define CP_WAIT0()  asm volatile("cp.async.wait_group 0;" ::: "memory")

// m16n8k16 bf16 mma. gid=lane>>2, tig=lane&3.
__device__ __forceinline__ void mma_bf16(float& d0, float& d1, float& d2, float& d3,
                                         uint32_t a0, uint32_t a1, uint32_t a2, uint32_t a3,
                                         uint32_t b0, uint32_t b1)
{
    asm volatile("mma.sync.aligned.m16n8k16.row.col.f32.bf16.bf16.f32 "
                 "{%0,%1,%2,%3}, {%4,%5,%6,%7}, {%8,%9}, {%0,%1,%2,%3};"
                 : "+f"(d0), "+f"(d1), "+f"(d2), "+f"(d3)
                 : "r"(a0), "r"(a1), "r"(a2), "r"(a3), "r"(b0), "r"(b1));
}

// ---------------------------------------------------------------------------
// Kernel 1: QKV projection, fp32 FFMA (exact), writing preconverted bf16
// hi/lo planes: q,k as [b][n][c2]; v transposed as [b][c][n2].
// ---------------------------------------------------------------------------
__global__ __launch_bounds__(256) void qkv_kernel(
    const float* __restrict__ x,
    const float* __restrict__ Wq, const float* __restrict__ bq,
    const float* __restrict__ Wk, const float* __restrict__ bk,
    const float* __restrict__ Wv, const float* __restrict__ bv)
{
    extern __shared__ float sm[];
    float* xs  = sm;                   // [128 ci][QK_STRIDE] cols = n
    float* wst = sm + 128 * QK_STRIDE; // [128 ci][QK_STRIDE] cols = o

    const int b   = blockIdx.y;
    const int n0  = blockIdx.x * 128;
    const int tid = threadIdx.x;
    const int ty  = tid >> 4;
    const int tx  = tid & 15;

    for (int i = tid; i < 128 * 128; i += 256) {
        int ci = i >> 7, n = i & 127;
        xs[ci * QK_STRIDE + n] = x[((size_t)b * Cch + ci) * Nn + n0 + n];
    }

    const float* Ws[3]   = {Wq, Wk, Wv};
    const float* bias[3] = {bq, bk, bv};

    for (int m = 0; m < 3; m++) {
        __syncthreads();
        const float* W = Ws[m];
        for (int i = tid; i < 128 * 128; i += 256) {
            int o = i >> 7, ci = i & 127;
            wst[ci * QK_STRIDE + o] = W[i];
        }
        __syncthreads();

        float acc[8][8];
        #pragma unroll
        for (int i = 0; i < 8; i++)
            #pragma unroll
            for (int u = 0; u < 8; u++) acc[i][u] = 0.f;

        #pragma unroll 4
        for (int ci = 0; ci < 128; ci++) {
            float4 w0 = *(const float4*)&wst[ci * QK_STRIDE + ty * 8];
            float4 w1 = *(const float4*)&wst[ci * QK_STRIDE + ty * 8 + 4];
            float4 x0 = *(const float4*)&xs [ci * QK_STRIDE + tx * 8];
            float4 x1 = *(const float4*)&xs [ci * QK_STRIDE + tx * 8 + 4];
            float wf[8] = {w0.x, w0.y, w0.z, w0.w, w1.x, w1.y, w1.z, w1.w};
            float xf[8] = {x0.x, x0.y, x0.z, x0.w, x1.x, x1.y, x1.z, x1.w};
            #pragma unroll
            for (int i = 0; i < 8; i++)
                #pragma unroll
                for (int u = 0; u < 8; u++)
                    acc[i][u] += wf[i] * xf[u];
        }

        float bvals[8];
        #pragma unroll
        for (int i = 0; i < 8; i++) bvals[i] = bias[m][ty * 8 + i];

        if (m < 2) {   // q,k -> [b][n][c2] hi/lo planes (pack channel pairs)
            uint32_t* ghi = (m == 0 ? g_qhi : g_khi) + (size_t)b * Nn * 64;
            uint32_t* glo = (m == 0 ? g_qlo : g_klo) + (size_t)b * Nn * 64;
            #pragma unroll
            for (int u = 0; u < 8; u++) {
                int n = n0 + tx * 8 + u;
                uint32_t hw[4], lw[4];
                #pragma unroll
                for (int i2 = 0; i2 < 4; i2++) {
                    float a0 = acc[2 * i2][u]     + bvals[2 * i2];
                    float a1 = acc[2 * i2 + 1][u] + bvals[2 * i2 + 1];
                    float h0 = rb16(a0), h1 = rb16(a1);
                    hw[i2] = pack_bf16(h0, h1);
                    lw[i2] = pack_bf16(a0 - h0, a1 - h1);
                }
                *(uint4*)&ghi[(size_t)n * 64 + ty * 4] = *(uint4*)hw;
                *(uint4*)&glo[(size_t)n * 64 + ty * 4] = *(uint4*)lw;
            }
        } else {       // v -> [b][c][n2] hi/lo planes (pack key pairs)
            uint32_t* ghi = g_vhi + (size_t)b * Cch * (Nn / 2);
            uint32_t* glo = g_vlo + (size_t)b * Cch * (Nn / 2);
            #pragma unroll
            for (int i = 0; i < 8; i++) {
                int c = ty * 8 + i;
                float bb = bvals[i];
                uint32_t hw[4], lw[4];
                #pragma unroll
                for (int u2 = 0; u2 < 4; u2++) {
                    float a0 = acc[i][2 * u2]     + bb;
                    float a1 = acc[i][2 * u2 + 1] + bb;
                    float h0 = rb16(a0), h1 = rb16(a1);
                    hw[u2] = pack_bf16(h0, h1);
                    lw[u2] = pack_bf16(a0 - h0, a1 - h1);
                }
                *(uint4*)&ghi[(size_t)c * (Nn / 2) + n0 / 2 + tx * 4] = *(uint4*)hw;
                *(uint4*)&glo[(size_t)c * (Nn / 2) + n0 / 2 + tx * 4] = *(uint4*)lw;
            }
        }
    }
}

// ---------------------------------------------------------------------------
// Kernel 2: per-(b,c) spatial mean of x.
// ---------------------------------------------------------------------------
__global__ __launch_bounds__(128) void se_mean_kernel(const float* __restrict__ x)
{
    const int bc  = blockIdx.x;
    const int tid = threadIdx.x;
    __shared__ float red[128];
    float s = 0.f;
    for (int t = tid; t < Nn; t += 128) s += x[(size_t)bc * Nn + t];
    red[tid] = s;
    __syncthreads();
    for (int off = 64; off > 0; off >>= 1) {
        if (tid < off) red[tid] += red[tid + off];
        __syncthreads();
    }
    if (tid == 0) g_mean[bc] = red[0] * (1.f / (float)Nn);
}

// ---------------------------------------------------------------------------
// Kernel 3: SE MLP.
// ---------------------------------------------------------------------------
__global__ __launch_bounds__(128) void se_mlp_kernel(
    const float* __restrict__ w1, const float* __restrict__ w2)
{
    __shared__ float h[Bb][Cch / REDr];
    const int tid = threadIdx.x;
    if (tid < Bb * (Cch / REDr)) {
        int b = tid >> 3, r = tid & 7;
        float s = 0.f;
        for (int c = 0; c < Cch; c++) s += g_mean[b * Cch + c] * w1[r * Cch + c];
        h[b][r] = fmaxf(s, 0.f);
    }
    __syncthreads();
    for (int idx = tid; idx < Bb * Cch; idx += 128) {
        int b = idx >> 7, c = idx & 127;
        float s = 0.f;
        #pragma unroll
        for (int r = 0; r < Cch / REDr; r++) s += h[b][r] * w2[c * (Cch / REDr) + r];
        g_y[idx] = 1.f / (1.f + __expf(-s));
    }
}

// ---------------------------------------------------------------------------
// Kernel 4: flash attention, bf16x3 S + bf16-split PV, cp.async double-buffer.
// 256 threads / 8 warps; warp owns 16 query rows; Q frags in registers.
// Per tile: issue cp.async for tile t+1, compute on tile t (overlapped).
// Grid (18, 8) = 144 CTAs, 1 wave.
// ---------------------------------------------------------------------------
__global__ __launch_bounds__(256, 1) void attn_kernel(
    const float* __restrict__ x,
    const float* __restrict__ gamma,
    float* __restrict__ out)
{
    extern __shared__ uint32_t smu[];
    const uint32_t smb = smem_u32(smu);

    const int b    = blockIdx.y;
    const int m0   = blockIdx.x * BM;
    const int tid  = threadIdx.x;
    const int wid  = tid >> 5;
    const int lane = tid & 31;
    const int gid  = lane >> 2;
    const int tig  = lane & 3;
    const int wr   = wid * 16;

    const uint32_t* qhi = g_qhi + (size_t)b * Nn * 64;
    const uint32_t* qlo = g_qlo + (size_t)b * Nn * 64;
    const uint32_t* khi = g_khi + (size_t)b * Nn * 64;
    const uint32_t* klo = g_klo + (size_t)b * Nn * 64;
    const uint32_t* vhi = g_vhi + (size_t)b * Cch * (Nn / 2);
    const uint32_t* vlo = g_vlo + (size_t)b * Cch * (Nn / 2);

    // Stage loads for tile t into buffer bi (pure cp.async, 16/thread)
    auto stage = [&](int t, int bi) {
        const int n0 = t * BN;
        #pragma unroll
        for (int ii = 0; ii < 8; ii++) {           // K: 2048 chunks of 16B
            int i = ii * 256 + tid;
            int plane = i >> 10, row = (i >> 4) & 63, seg = i & 15;
            uint32_t dst = smb + (U_K0 + bi * KBUF + plane * KPLANE + row * KSU + seg * 4) * 4;
            const uint32_t* src = (plane ? klo : khi) + ((size_t)(n0 + row) * 64 + seg * 4);
            CP_ASYNC16(dst, src);
        }
        #pragma unroll
        for (int ii = 0; ii < 8; ii++) {           // V: 2048 chunks of 16B
            int i = ii * 256 + tid;
            int plane = i >> 10, c = (i >> 3) & 127, seg = i & 7;
            uint32_t dst = smb + (U_V0 + bi * VBUF + plane * VPLANE + c * VSU + seg * 4) * 4;
            const uint32_t* src = (plane ? vlo : vhi) + ((size_t)c * (Nn / 2) + n0 / 2 + seg * 4);
            CP_ASYNC16(dst, src);
        }
    };

    // Q fragments (hi/lo) straight from gmem, one time.
    uint32_t qh[8][4], ql[8][4];
    {
        const size_t r0 = (size_t)(m0 + wr + gid) * 64;
        const size_t r1 = (size_t)(m0 + wr + gid + 8) * 64;
        #pragma unroll
        for (int kc = 0; kc < 8; kc++) {
            qh[kc][0] = qhi[r0 + kc * 8 + tig];
            qh[kc][1] = qhi[r1 + kc * 8 + tig];
            qh[kc][2] = qhi[r0 + kc * 8 + tig + 4];
            qh[kc][3] = qhi[r1 + kc * 8 + tig + 4];
            ql[kc][0] = qlo[r0 + kc * 8 + tig];
            ql[kc][1] = qlo[r1 + kc * 8 + tig];
            ql[kc][2] = qlo[r0 + kc * 8 + tig + 4];
            ql[kc][3] = qlo[r1 + kc * 8 + tig + 4];
        }
    }

    stage(0, 0);
    CP_COMMIT();

    float o_acc[16][4];
    #pragma unroll
    for (int n = 0; n < 16; n++) {
        o_acc[n][0] = 0.f; o_acc[n][1] = 0.f; o_acc[n][2] = 0.f; o_acc[n][3] = 0.f;
    }
    float l_lo = 0.f, l_hi = 0.f;

    for (int t = 0; t < NTIL; t++) {
        const int bi = t & 1;
        if (t + 1 < NTIL) {
            stage(t + 1, bi ^ 1);   // prior reads of that buffer finished at end of t-1
            CP_COMMIT();
            CP_WAIT1();             // tile t's group complete
        } else {
            CP_WAIT0();
        }
        __syncthreads();

        const uint32_t Kb = U_K0 + bi * KBUF;      // hi at Kb, lo at Kb+KPLANE
        const uint32_t Vb = U_V0 + bi * VBUF;      // hi at Vb, lo at Vb+VPLANE

        // ---- S = Q K^T (bf16x3): 16 rows x 64 keys ----
        float sacc[8][4];
        #pragma unroll
        for (int n = 0; n < 8; n++) {
            sacc[n][0] = 0.f; sacc[n][1] = 0.f; sacc[n][2] = 0.f; sacc[n][3] = 0.f;
        }
        #pragma unroll
        for (int kc = 0; kc < 8; kc++) {
            #pragma unroll
            for (int nch = 0; nch < 8; nch++) {
                int krow = Kb + (nch * 8 + gid) * KSU + kc * 8 + tig;
                uint32_t bh0 = smu[krow];
                uint32_t bh1 = smu[krow + 4];
                uint32_t bl0 = smu[krow + KPLANE];
                uint32_t bl1 = smu[krow + KPLANE + 4];
                mma_bf16(sacc[nch][0], sacc[nch][1], sacc[nch][2], sacc[nch][3],
                         qh[kc][0], qh[kc][1], qh[kc][2], qh[kc][3], bh0, bh1);
                mma_bf16(sacc[nch][0], sacc[nch][1], sacc[nch][2], sacc[nch][3],
                         ql[kc][0], ql[kc][1], ql[kc][2], ql[kc][3], bh0, bh1);
                mma_bf16(sacc[nch][0], sacc[nch][1], sacc[nch][2], sacc[nch][3],
                         qh[kc][0], qh[kc][1], qh[kc][2], qh[kc][3], bl0, bl1);
            }
        }

        // ---- p = exp(s) -> bf16; l sums the ROUNDED p (ratio consistency) ----
        #pragma unroll
        for (int nch = 0; nch < 8; nch++) {
            float p0 = __expf(sacc[nch][0]), p1 = __expf(sacc[nch][1]);
            float p2 = __expf(sacc[nch][2]), p3 = __expf(sacc[nch][3]);
            l_lo += rb16(p0) + rb16(p1);
            l_hi += rb16(p2) + rb16(p3);
            smu[U_PS + (wr + gid)     * PSU + nch * 4 + tig] = pack_bf16(p0, p1);
            smu[U_PS + (wr + gid + 8) * PSU + nch * 4 + tig] = pack_bf16(p2, p3);
        }
        __syncwarp();   // Ps rows are warp-private

        uint32_t pf[4][4];
        #pragma unroll
        for (int kc = 0; kc < 4; kc++) {
            pf[kc][0] = smu[U_PS + (wr + gid)     * PSU + kc * 8 + tig];
            pf[kc][1] = smu[U_PS + (wr + gid + 8) * PSU + kc * 8 + tig];
            pf[kc][2] = smu[U_PS + (wr + gid)     * PSU + kc * 8 + tig + 4];
            pf[kc][3] = smu[U_PS + (wr + gid + 8) * PSU + kc * 8 + tig + 4];
        }

        // ---- O += P (Vhi + Vlo) ----
        #pragma unroll
        for (int nch = 0; nch < 16; nch++) {
            #pragma unroll
            for (int kc = 0; kc < 4; kc++) {
                int vrow = Vb + (nch * 8 + gid) * VSU + kc * 8 + tig;
                uint32_t vh0 = smu[vrow];
                uint32_t vh1 = smu[vrow + 4];
                uint32_t vl0 = smu[vrow + VPLANE];
                uint32_t vl1 = smu[vrow + VPLANE + 4];
                mma_bf16(o_acc[nch][0], o_acc[nch][1], o_acc[nch][2], o_acc[nch][3],
                         pf[kc][0], pf[kc][1], pf[kc][2], pf[kc][3], vh0, vh1);
                mma_bf16(o_acc[nch][0], o_acc[nch][1], o_acc[nch][2], o_acc[nch][3],
                         pf[kc][0], pf[kc][1], pf[kc][2], pf[kc][3], vl0, vl1);
            }
        }
        __syncthreads();   // buffer bi free for tile t+2's cp.async
    }

    // Row sums across the quad
    l_lo += __shfl_xor_sync(0xFFFFFFFF, l_lo, 1);
    l_lo += __shfl_xor_sync(0xFFFFFFFF, l_lo, 2);
    l_hi += __shfl_xor_sync(0xFFFFFFFF, l_hi, 1);
    l_hi += __shfl_xor_sync(0xFFFFFFFF, l_hi, 2);
    const float inv_lo = 1.f / l_lo;
    const float inv_hi = 1.f / l_hi;

    // Epilogue
    const float g = gamma[0];
    const int i_lo = m0 + wr + gid;
    const int i_hi = i_lo + 8;
    const float* yb = g_y + b * Cch;
    #pragma unroll
    for (int nch = 0; nch < 16; nch++) {
        int c0 = nch * 8 + 2 * tig;
        int c1 = c0 + 1;
        size_t i00 = ((size_t)b * Cch + c0) * Nn;
        size_t i01 = ((size_t)b * Cch + c1) * Nn;
        out[i00 + i_lo] = g * (o_acc[nch][0] * inv_lo) + x[i00 + i_lo] * yb[c0];
        out[i01 + i_lo] = g * (o_acc[nch][1] * inv_lo) + x[i01 + i_lo] * yb[c1];
        out[i00 + i_hi] = g * (o_acc[nch][2] * inv_hi) + x[i00 + i_hi] * yb[c0];
        out[i01 + i_hi] = g * (o_acc[nch][3] * inv_hi) + x[i01 + i_hi] * yb[c1];
    }
}

// ---------------------------------------------------------------------------
extern "C" void kernel_launch(void* const* d_in, const int* in_sizes, int n_in,
                              void* d_out, int out_size)
{
    const float* x     = (const float*)d_in[0];
    const float* Wq    = (const float*)d_in[1];
    const float* bq    = (const float*)d_in[2];
    const float* Wk    = (const float*)d_in[3];
    const float* bk    = (const float*)d_in[4];
    const float* Wv    = (const float*)d_in[5];
    const float* bv    = (const float*)d_in[6];
    const float* se_w1 = (const float*)d_in[7];
    const float* se_w2 = (const float*)d_in[8];
    const float* gamma = (const float*)d_in[9];
    float* out = (float*)d_out;

    const int QKV_SMEM = 2 * 128 * QK_STRIDE * (int)sizeof(float);   // 135168

    cudaFuncSetAttribute(qkv_kernel,  cudaFuncAttributeMaxDynamicSharedMemorySize, QKV_SMEM);
    cudaFuncSetAttribute(attn_kernel, cudaFuncAttributeMaxDynamicSharedMemorySize, ATTN_SMEM);

    qkv_kernel<<<dim3(Nn / 128, Bb), 256, QKV_SMEM>>>(x, Wq, bq, Wk, bk, Wv, bv);
    se_mean_kernel<<<Bb * Cch, 128>>>(x);
    se_mlp_kernel<<<1, 128>>>(se_w1, se_w2);
    attn_kernel<<<dim3(Nn / BM, Bb), 256, ATTN_SMEM>>>(x, gamma, out);
}

// round 13
// speedup vs baseline: 1.4222x; 1.4222x over previous
#include <cuda_runtime.h>
#include <cuda_bf16.h>
#include <cstdint>

// Problem constants
#define Bb   8
#define Cch  128
#define Nn   2304      // 48*48
#define REDr 16
#define BM   128       // query tile rows per CTA
#define BN   64        // key tile per iteration
#define NTIL (Nn / BN) // 36
#define QK_STRIDE 132  // fp32 qkv-projection smem stride

// attn smem (uint32 word offsets); bf16 pairs packed in uint32.
// K rows [key][c2]: 64 data words + 4 pad = 68 (KSU). Plane = 64*68 = 4352.
// V rows [chan][key2]: 32 data words + 4 pad = 36 (VSU). Plane = 128*36.
#define KSU  68
#define VSU  36
#define PSU  36
#define KPLANE (64 * KSU)     // 4352
#define VPLANE (128 * VSU)    // 4608
#define KBUF   (2 * KPLANE)   // hi+lo
#define VBUF   (2 * VPLANE)
#define U_K0   0
#define U_V0   (2 * KBUF)             // 17408
#define U_PS   (U_V0 + 2 * VBUF)      // 35840
#define ATTN_WORDS (U_PS + 128 * PSU) // 40448
#define ATTN_SMEM  (ATTN_WORDS * 4)   // 161792 B

// fp32 projections (qkv output; convert kernel input)
__device__ float g_q [Bb * Nn * Cch];   // [b][n][c]
__device__ float g_k [Bb * Nn * Cch];   // [b][n][c]
__device__ float g_vt[Bb * Cch * Nn];   // [b][c][n]
// preconverted bf16 hi/lo planes (packed pairs in uint32)
__device__ uint32_t g_qhi[Bb * Nn * 64];        // [b][n][c2]
__device__ uint32_t g_qlo[Bb * Nn * 64];
__device__ uint32_t g_khi[Bb * Nn * 64];
__device__ uint32_t g_klo[Bb * Nn * 64];
__device__ uint32_t g_vhi[Bb * Cch * (Nn / 2)]; // [b][c][n2]
__device__ uint32_t g_vlo[Bb * Cch * (Nn / 2)];
__device__ float g_mean[Bb * Cch];
__device__ float g_y[Bb * Cch];

__device__ __forceinline__ uint32_t smem_u32(const void* p) {
    uint32_t a;
    asm("{ .reg .u64 t; cvta.to.shared.u64 t, %1; cvt.u32.u64 %0, t; }" : "=r"(a) : "l"(p));
    return a;
}
// pack two floats to bf16x2 (rn): first arg -> low half (even element)
__device__ __forceinline__ uint32_t pack_bf16(float lo, float hi) {
    uint32_t r;
    asm("cvt.rn.bf16x2.f32 %0, %1, %2;" : "=r"(r) : "f"(hi), "f"(lo));
    return r;
}
__device__ __forceinline__ float rb16(float a) {
    return __bfloat162float(__float2bfloat16(a));
}
#define CP_ASYNC16(dst_u32, src_ptr) \
    asm volatile("cp.async.cg.shared.global [%0], [%1], 16;" :: "r"(dst_u32), "l"(src_ptr))
#define CP_COMMIT() asm volatile("cp.async.commit_group;" ::: "memory")
#define CP_WAIT1()  asm volatile("cp.async.wait_group 1;" ::: "memory")
#define CP_WAIT0()  asm volatile("cp.async.wait_group 0;" ::: "memory")
#define LDSM_X4(r0, r1, r2, r3, addr) \
    asm volatile("ldmatrix.sync.aligned.m8n8.x4.shared.b16 {%0,%1,%2,%3}, [%4];" \
                 : "=r"(r0), "=r"(r1), "=r"(r2), "=r"(r3) : "r"(addr))

// m16n8k16 bf16 mma. gid=lane>>2, tig=lane&3.
__device__ __forceinline__ void mma_bf16(float& d0, float& d1, float& d2, float& d3,
                                         uint32_t a0, uint32_t a1, uint32_t a2, uint32_t a3,
                                         uint32_t b0, uint32_t b1)
{
    asm volatile("mma.sync.aligned.m16n8k16.row.col.f32.bf16.bf16.f32 "
                 "{%0,%1,%2,%3}, {%4,%5,%6,%7}, {%8,%9}, {%0,%1,%2,%3};"
                 : "+f"(d0), "+f"(d1), "+f"(d2), "+f"(d3)
                 : "r"(a0), "r"(a1), "r"(a2), "r"(a3), "r"(b0), "r"(b1));
}

// ---------------------------------------------------------------------------
// Kernel 1: QKV projection, fp32 FFMA (exact; R9 version verbatim).
// q,k -> [b][n][c] fp32; v -> [b][c][n] fp32.
// ---------------------------------------------------------------------------
__global__ __launch_bounds__(256) void qkv_kernel(
    const float* __restrict__ x,
    const float* __restrict__ Wq, const float* __restrict__ bq,
    const float* __restrict__ Wk, const float* __restrict__ bk,
    const float* __restrict__ Wv, const float* __restrict__ bv)
{
    extern __shared__ float sm[];
    float* xs  = sm;                   // [128 ci][QK_STRIDE] cols = n
    float* wst = sm + 128 * QK_STRIDE; // [128 ci][QK_STRIDE] cols = o

    const int b   = blockIdx.y;
    const int n0  = blockIdx.x * 128;
    const int tid = threadIdx.x;
    const int ty  = tid >> 4;
    const int tx  = tid & 15;

    for (int i = tid; i < 128 * 128; i += 256) {
        int ci = i >> 7, n = i & 127;
        xs[ci * QK_STRIDE + n] = x[((size_t)b * Cch + ci) * Nn + n0 + n];
    }

    const float* Ws[3]   = {Wq, Wk, Wv};
    const float* bias[3] = {bq, bk, bv};

    for (int m = 0; m < 3; m++) {
        __syncthreads();
        const float* W = Ws[m];
        for (int i = tid; i < 128 * 128; i += 256) {
            int o = i >> 7, ci = i & 127;
            wst[ci * QK_STRIDE + o] = W[i];
        }
        __syncthreads();

        float acc[8][8];
        #pragma unroll
        for (int i = 0; i < 8; i++)
            #pragma unroll
            for (int u = 0; u < 8; u++) acc[i][u] = 0.f;

        #pragma unroll 4
        for (int ci = 0; ci < 128; ci++) {
            float4 w0 = *(const float4*)&wst[ci * QK_STRIDE + ty * 8];
            float4 w1 = *(const float4*)&wst[ci * QK_STRIDE + ty * 8 + 4];
            float4 x0 = *(const float4*)&xs [ci * QK_STRIDE + tx * 8];
            float4 x1 = *(const float4*)&xs [ci * QK_STRIDE + tx * 8 + 4];
            float wf[8] = {w0.x, w0.y, w0.z, w0.w, w1.x, w1.y, w1.z, w1.w};
            float xf[8] = {x0.x, x0.y, x0.z, x0.w, x1.x, x1.y, x1.z, x1.w};
            #pragma unroll
            for (int i = 0; i < 8; i++)
                #pragma unroll
                for (int u = 0; u < 8; u++)
                    acc[i][u] += wf[i] * xf[u];
        }

        float bvals[8];
        #pragma unroll
        for (int i = 0; i < 8; i++) bvals[i] = bias[m][ty * 8 + i];

        if (m < 2) {   // q,k: [b][n][c]
            float* outp = (m == 0 ? g_q : g_k) + (size_t)b * Nn * Cch;
            #pragma unroll
            for (int u = 0; u < 8; u++) {
                int n = n0 + tx * 8 + u;
                float4 s0 = {acc[0][u] + bvals[0], acc[1][u] + bvals[1],
                             acc[2][u] + bvals[2], acc[3][u] + bvals[3]};
                float4 s1 = {acc[4][u] + bvals[4], acc[5][u] + bvals[5],
                             acc[6][u] + bvals[6], acc[7][u] + bvals[7]};
                *(float4*)&outp[(size_t)n * Cch + ty * 8]     = s0;
                *(float4*)&outp[(size_t)n * Cch + ty * 8 + 4] = s1;
            }
        } else {       // v: transposed [b][c][n]
            float* outp = g_vt + (size_t)b * Cch * Nn;
            #pragma unroll
            for (int i = 0; i < 8; i++) {
                int c = ty * 8 + i;
                float bb = bvals[i];
                float4 s0 = {acc[i][0] + bb, acc[i][1] + bb, acc[i][2] + bb, acc[i][3] + bb};
                float4 s1 = {acc[i][4] + bb, acc[i][5] + bb, acc[i][6] + bb, acc[i][7] + bb};
                *(float4*)&outp[(size_t)c * Nn + n0 + tx * 8]     = s0;
                *(float4*)&outp[(size_t)c * Nn + n0 + tx * 8 + 4] = s1;
            }
        }
    }
}

// ---------------------------------------------------------------------------
// Kernel 1b: streaming fp32 -> packed bf16 hi/lo planes. Pure bandwidth.
// ---------------------------------------------------------------------------
__global__ __launch_bounds__(256) void convert_kernel()
{
    const int W1 = Bb * Nn * 64;            // q/k words
    const int W2 = Bb * Cch * (Nn / 2);     // v words
    const int stride = gridDim.x * blockDim.x;
    for (int w = blockIdx.x * blockDim.x + threadIdx.x; w < W1; w += stride) {
        float2 q = ((const float2*)g_q)[w];
        float h0 = rb16(q.x), h1 = rb16(q.y);
        g_qhi[w] = pack_bf16(h0, h1);
        g_qlo[w] = pack_bf16(q.x - h0, q.y - h1);
        float2 k = ((const float2*)g_k)[w];
        float g0 = rb16(k.x), g1 = rb16(k.y);
        g_khi[w] = pack_bf16(g0, g1);
        g_klo[w] = pack_bf16(k.x - g0, k.y - g1);
    }
    for (int w = blockIdx.x * blockDim.x + threadIdx.x; w < W2; w += stride) {
        float2 v = ((const float2*)g_vt)[w];
        float h0 = rb16(v.x), h1 = rb16(v.y);
        g_vhi[w] = pack_bf16(h0, h1);
        g_vlo[w] = pack_bf16(v.x - h0, v.y - h1);
    }
}

// ---------------------------------------------------------------------------
// Kernel 2: per-(b,c) spatial mean of x.
// ---------------------------------------------------------------------------
__global__ __launch_bounds__(128) void se_mean_kernel(const float* __restrict__ x)
{
    const int bc  = blockIdx.x;
    const int tid = threadIdx.x;
    __shared__ float red[128];
    float s = 0.f;
    for (int t = tid; t < Nn; t += 128) s += x[(size_t)bc * Nn + t];
    red[tid] = s;
    __syncthreads();
    for (int off = 64; off > 0; off >>= 1) {
        if (tid < off) red[tid] += red[tid + off];
        __syncthreads();
    }
    if (tid == 0) g_mean[bc] = red[0] * (1.f / (float)Nn);
}

// ---------------------------------------------------------------------------
// Kernel 3: SE MLP.
// ---------------------------------------------------------------------------
__global__ __launch_bounds__(128) void se_mlp_kernel(
    const float* __restrict__ w1, const float* __restrict__ w2)
{
    __shared__ float h[Bb][Cch / REDr];
    const int tid = threadIdx.x;
    if (tid < Bb * (Cch / REDr)) {
        int b = tid >> 3, r = tid & 7;
        float s = 0.f;
        for (int c = 0; c < Cch; c++) s += g_mean[b * Cch + c] * w1[r * Cch + c];
        h[b][r] = fmaxf(s, 0.f);
    }
    __syncthreads();
    for (int idx = tid; idx < Bb * Cch; idx += 128) {
        int b = idx >> 7, c = idx & 127;
        float s = 0.f;
        #pragma unroll
        for (int r = 0; r < Cch / REDr; r++) s += h[b][r] * w2[c * (Cch / REDr) + r];
        g_y[idx] = 1.f / (1.f + __expf(-s));
    }
}

// ---------------------------------------------------------------------------
// Kernel 4: flash attention, bf16x3 S + bf16-split PV, cp.async double-buffer,
// ldmatrix.x4 fragment loads. 256 threads / 8 warps; warp owns 16 query rows.
// ---------------------------------------------------------------------------
__global__ __launch_bounds__(256, 1) void attn_kernel(
    const float* __restrict__ x,
    const float* __restrict__ gamma,
    float* __restrict__ out)
{
    extern __shared__ uint32_t smu[];
    const uint32_t smb = smem_u32(smu);

    const int b    = blockIdx.y;
    const int m0   = blockIdx.x * BM;
    const int tid  = threadIdx.x;
    const int wid  = tid >> 5;
    const int lane = tid & 31;
    const int gid  = lane >> 2;
    const int tig  = lane & 3;
    const int wr   = wid * 16;

    const uint32_t* qhi = g_qhi + (size_t)b * Nn * 64;
    const uint32_t* qlo = g_qlo + (size_t)b * Nn * 64;
    const uint32_t* khi = g_khi + (size_t)b * Nn * 64;
    const uint32_t* klo = g_klo + (size_t)b * Nn * 64;
    const uint32_t* vhi = g_vhi + (size_t)b * Cch * (Nn / 2);
    const uint32_t* vlo = g_vlo + (size_t)b * Cch * (Nn / 2);

    // ldmatrix lane-address components (word units):
    // group g = lane>>3: tiles [nch0-half0, nch0-half1, nch1-half0, nch1-half1]
    const int rowin = lane & 7;
    const int nchoff = lane >> 4;          // 0/1 -> which nch of the pair
    const int halfo  = (lane >> 3) & 1;    // 0/1 -> b0/b1 halves
    const int laneK = (nchoff * 8 + rowin) * KSU + halfo * 4;
    const int laneV = (nchoff * 8 + rowin) * VSU + halfo * 4;
    // P A-frag tiles: [rows0-7 k0, rows8-15 k0, rows0-7 k1, rows8-15 k1]
    const int laneP = (wr + ((lane >> 3) & 1) * 8 + rowin) * PSU + (lane >> 4) * 4;

    auto stage = [&](int t, int bi) {
        const int n0 = t * BN;
        #pragma unroll
        for (int ii = 0; ii < 8; ii++) {           // K planes: 2048 x 16B
            int i = ii * 256 + tid;
            int plane = i >> 10, row = (i >> 4) & 63, seg = i & 15;
            uint32_t dst = smb + (U_K0 + bi * KBUF + plane * KPLANE + row * KSU + seg * 4) * 4;
            const uint32_t* src = (plane ? klo : khi) + ((size_t)(n0 + row) * 64 + seg * 4);
            CP_ASYNC16(dst, src);
        }
        #pragma unroll
        for (int ii = 0; ii < 8; ii++) {           // V planes: 2048 x 16B
            int i = ii * 256 + tid;
            int plane = i >> 10, c = (i >> 3) & 127, seg = i & 7;
            uint32_t dst = smb + (U_V0 + bi * VBUF + plane * VPLANE + c * VSU + seg * 4) * 4;
            const uint32_t* src = (plane ? vlo : vhi) + ((size_t)c * (Nn / 2) + n0 / 2 + seg * 4);
            CP_ASYNC16(dst, src);
        }
    };

    // Q fragments (hi/lo) straight from gmem, once.
    uint32_t qh[8][4], ql[8][4];
    {
        const size_t r0 = (size_t)(m0 + wr + gid) * 64;
        const size_t r1 = (size_t)(m0 + wr + gid + 8) * 64;
        #pragma unroll
        for (int kc = 0; kc < 8; kc++) {
            qh[kc][0] = qhi[r0 + kc * 8 + tig];
            qh[kc][1] = qhi[r1 + kc * 8 + tig];
            qh[kc][2] = qhi[r0 + kc * 8 + tig + 4];
            qh[kc][3] = qhi[r1 + kc * 8 + tig + 4];
            ql[kc][0] = qlo[r0 + kc * 8 + tig];
            ql[kc][1] = qlo[r1 + kc * 8 + tig];
            ql[kc][2] = qlo[r0 + kc * 8 + tig + 4];
            ql[kc][3] = qlo[r1 + kc * 8 + tig + 4];
        }
    }

    stage(0, 0);
    CP_COMMIT();

    float o_acc[16][4];
    #pragma unroll
    for (int n = 0; n < 16; n++) {
        o_acc[n][0] = 0.f; o_acc[n][1] = 0.f; o_acc[n][2] = 0.f; o_acc[n][3] = 0.f;
    }
    float l_lo = 0.f, l_hi = 0.f;

    for (int t = 0; t < NTIL; t++) {
        const int bi = t & 1;
        if (t + 1 < NTIL) {
            stage(t + 1, bi ^ 1);
            CP_COMMIT();
            CP_WAIT1();
        } else {
            CP_WAIT0();
        }
        __syncthreads();

        const uint32_t Kb = U_K0 + bi * KBUF;
        const uint32_t Vb = U_V0 + bi * VBUF;

        // ---- S = Q K^T (bf16x3), ldmatrix fragment loads ----
        float sacc[8][4];
        #pragma unroll
        for (int n = 0; n < 8; n++) {
            sacc[n][0] = 0.f; sacc[n][1] = 0.f; sacc[n][2] = 0.f; sacc[n][3] = 0.f;
        }
        #pragma unroll
        for (int kc = 0; kc < 8; kc++) {
            #pragma unroll
            for (int np = 0; np < 4; np++) {
                uint32_t a_hi = smb + (Kb + np * (16 * KSU) + kc * 8 + laneK) * 4;
                uint32_t h0, h1, h2, h3, L0, L1, L2, L3;
                LDSM_X4(h0, h1, h2, h3, a_hi);
                LDSM_X4(L0, L1, L2, L3, a_hi + KPLANE * 4);
                int na = np * 2, nb = np * 2 + 1;
                mma_bf16(sacc[na][0], sacc[na][1], sacc[na][2], sacc[na][3],
                         qh[kc][0], qh[kc][1], qh[kc][2], qh[kc][3], h0, h1);
                mma_bf16(sacc[na][0], sacc[na][1], sacc[na][2], sacc[na][3],
                         ql[kc][0], ql[kc][1], ql[kc][2], ql[kc][3], h0, h1);
                mma_bf16(sacc[na][0], sacc[na][1], sacc[na][2], sacc[na][3],
                         qh[kc][0], qh[kc][1], qh[kc][2], qh[kc][3], L0, L1);
                mma_bf16(sacc[nb][0], sacc[nb][1], sacc[nb][2], sacc[nb][3],
                         qh[kc][0], qh[kc][1], qh[kc][2], qh[kc][3], h2, h3);
                mma_bf16(sacc[nb][0], sacc[nb][1], sacc[nb][2], sacc[nb][3],
                         ql[kc][0], ql[kc][1], ql[kc][2], ql[kc][3], h2, h3);
                mma_bf16(sacc[nb][0], sacc[nb][1], sacc[nb][2], sacc[nb][3],
                         qh[kc][0], qh[kc][1], qh[kc][2], qh[kc][3], L2, L3);
            }
        }

        // ---- p = exp(s) -> bf16; l sums the ROUNDED p ----
        #pragma unroll
        for (int nch = 0; nch < 8; nch++) {
            float p0 = __expf(sacc[nch][0]), p1 = __expf(sacc[nch][1]);
            float p2 = __expf(sacc[nch][2]), p3 = __expf(sacc[nch][3]);
            l_lo += rb16(p0) + rb16(p1);
            l_hi += rb16(p2) + rb16(p3);
            smu[U_PS + (wr + gid)     * PSU + nch * 4 + tig] = pack_bf16(p0, p1);
            smu[U_PS + (wr + gid + 8) * PSU + nch * 4 + tig] = pack_bf16(p2, p3);
        }
        __syncwarp();   // Ps rows are warp-private

        uint32_t pf[4][4];
        #pragma unroll
        for (int kc = 0; kc < 4; kc++) {
            LDSM_X4(pf[kc][0], pf[kc][1], pf[kc][2], pf[kc][3],
                    smb + (U_PS + laneP + kc * 8) * 4);
        }

        // ---- O += P (Vhi + Vlo), ldmatrix fragment loads ----
        #pragma unroll
        for (int np = 0; np < 8; np++) {
            #pragma unroll
            for (int kc = 0; kc < 4; kc++) {
                uint32_t a_hi = smb + (Vb + np * (16 * VSU) + kc * 8 + laneV) * 4;
                uint32_t h0, h1, h2, h3, L0, L1, L2, L3;
                LDSM_X4(h0, h1, h2, h3, a_hi);
                LDSM_X4(L0, L1, L2, L3, a_hi + VPLANE * 4);
                int na = np * 2, nb = np * 2 + 1;
                mma_bf16(o_acc[na][0], o_acc[na][1], o_acc[na][2], o_acc[na][3],
                         pf[kc][0], pf[kc][1], pf[kc][2], pf[kc][3], h0, h1);
                mma_bf16(o_acc[na][0], o_acc[na][1], o_acc[na][2], o_acc[na][3],
                         pf[kc][0], pf[kc][1], pf[kc][2], pf[kc][3], L0, L1);
                mma_bf16(o_acc[nb][0], o_acc[nb][1], o_acc[nb][2], o_acc[nb][3],
                         pf[kc][0], pf[kc][1], pf[kc][2], pf[kc][3], h2, h3);
                mma_bf16(o_acc[nb][0], o_acc[nb][1], o_acc[nb][2], o_acc[nb][3],
                         pf[kc][0], pf[kc][1], pf[kc][2], pf[kc][3], L2, L3);
            }
        }
        __syncthreads();
    }

    // Row sums across the quad
    l_lo += __shfl_xor_sync(0xFFFFFFFF, l_lo, 1);
    l_lo += __shfl_xor_sync(0xFFFFFFFF, l_lo, 2);
    l_hi += __shfl_xor_sync(0xFFFFFFFF, l_hi, 1);
    l_hi += __shfl_xor_sync(0xFFFFFFFF, l_hi, 2);
    const float inv_lo = 1.f / l_lo;
    const float inv_hi = 1.f / l_hi;

    // Epilogue
    const float g = gamma[0];
    const int i_lo = m0 + wr + gid;
    const int i_hi = i_lo + 8;
    const float* yb = g_y + b * Cch;
    #pragma unroll
    for (int nch = 0; nch < 16; nch++) {
        int c0 = nch * 8 + 2 * tig;
        int c1 = c0 + 1;
        size_t i00 = ((size_t)b * Cch + c0) * Nn;
        size_t i01 = ((size_t)b * Cch + c1) * Nn;
        out[i00 + i_lo] = g * (o_acc[nch][0] * inv_lo) + x[i00 + i_lo] * yb[c0];
        out[i01 + i_lo] = g * (o_acc[nch][1] * inv_lo) + x[i01 + i_lo] * yb[c1];
        out[i00 + i_hi] = g * (o_acc[nch][2] * inv_hi) + x[i00 + i_hi] * yb[c0];
        out[i01 + i_hi] = g * (o_acc[nch][3] * inv_hi) + x[i01 + i_hi] * yb[c1];
    }
}

// ---------------------------------------------------------------------------
extern "C" void kernel_launch(void* const* d_in, const int* in_sizes, int n_in,
                              void* d_out, int out_size)
{
    const float* x     = (const float*)d_in[0];
    const float* Wq    = (const float*)d_in[1];
    const float* bq    = (const float*)d_in[2];
    const float* Wk    = (const float*)d_in[3];
    const float* bk    = (const float*)d_in[4];
    const float* Wv    = (const float*)d_in[5];
    const float* bv    = (const float*)d_in[6];
    const float* se_w1 = (const float*)d_in[7];
    const float* se_w2 = (const float*)d_in[8];
    const float* gamma = (const float*)d_in[9];
    float* out = (float*)d_out;

    const int QKV_SMEM = 2 * 128 * QK_STRIDE * (int)sizeof(float);   // 135168

    cudaFuncSetAttribute(qkv_kernel,  cudaFuncAttributeMaxDynamicSharedMemorySize, QKV_SMEM);
    cudaFuncSetAttribute(attn_kernel, cudaFuncAttributeMaxDynamicSharedMemorySize, ATTN_SMEM);

    qkv_kernel<<<dim3(Nn / 128, Bb), 256, QKV_SMEM>>>(x, Wq, bq, Wk, bk, Wv, bv);
    convert_kernel<<<592, 256>>>();
    se_mean_kernel<<<Bb * Cch, 128>>>(x);
    se_mlp_kernel<<<1, 128>>>(se_w1, se_w2);
    attn_kernel<<<dim3(Nn / BM, Bb), 256, ATTN_SMEM>>>(x, gamma, out);
}

// round 16
// speedup vs baseline: 2.0034x; 1.4087x over previous
#include <cuda_runtime.h>
#include <cuda_bf16.h>
#include <cstdint>

// Problem constants
#define Bb   8
#define Cch  128
#define Nn   2304      // 48*48
#define REDr 16
#define BM   128
#define BN   64
#define NTIL (Nn / BN) // 36
#define LOG2E 1.4426950408889634f

// ---- qkv-mma smem (word offsets): x planes [c][n2], W planes [o][c2] ----
#define XSU 68
#define WSU 68
#define XPLANE (128 * XSU)          // 8704
#define QKV_U_X 0
#define QKV_U_W (2 * XPLANE)        // 17408
#define QKV_WORDS (QKV_U_W + 2 * XPLANE)   // 34816
#define QKV_SMEM (QKV_WORDS * 4)           // 139264

// ---- attn smem (word offsets): K and V both [row][c2]-class, stride 68 ----
#define KSU  68
#define PSU  36
#define KPLANE (64 * KSU)     // 4352
#define KBUF   (2 * KPLANE)   // hi+lo = 8704
#define U_K0   0
#define U_V0   (2 * KBUF)             // 17408
#define U_PS   (U_V0 + 2 * KBUF)      // 34816
#define U_Y    (U_PS + 128 * PSU)     // 39424 (y: 128 floats, h: 8 floats)
#define ATTN_WORDS (U_Y + 136)
#define ATTN_SMEM  (ATTN_WORDS * 4)   // 158240 B

// Scratch: bf16 hi/lo planes (packed pairs), all [b][n][c2]
__device__ uint32_t g_qhi[Bb * Nn * 64];
__device__ uint32_t g_qlo[Bb * Nn * 64];
__device__ uint32_t g_khi[Bb * Nn * 64];
__device__ uint32_t g_klo[Bb * Nn * 64];
__device__ uint32_t g_vhi[Bb * Nn * 64];
__device__ uint32_t g_vlo[Bb * Nn * 64];
__device__ float g_mean[Bb * Cch];

__device__ __forceinline__ uint32_t smem_u32(const void* p) {
    uint32_t a;
    asm("{ .reg .u64 t; cvta.to.shared.u64 t, %1; cvt.u32.u64 %0, t; }" : "=r"(a) : "l"(p));
    return a;
}
__device__ __forceinline__ uint32_t pack_bf16(float lo, float hi) {
    uint32_t r;
    asm("cvt.rn.bf16x2.f32 %0, %1, %2;" : "=r"(r) : "f"(hi), "f"(lo));
    return r;
}
__device__ __forceinline__ float rb16(float a) {
    return __bfloat162float(__float2bfloat16(a));
}
#define CP_ASYNC16(dst_u32, src_ptr) \
    asm volatile("cp.async.cg.shared.global [%0], [%1], 16;" :: "r"(dst_u32), "l"(src_ptr))
#define CP_COMMIT() asm volatile("cp.async.commit_group;" ::: "memory")
#define CP_WAIT1()  asm volatile("cp.async.wait_group 1;" ::: "memory")
#define CP_WAIT0()  asm volatile("cp.async.wait_group 0;" ::: "memory")
#define LDSM_X4(r0, r1, r2, r3, addr) \
    asm volatile("ldmatrix.sync.aligned.m8n8.x4.shared.b16 {%0,%1,%2,%3}, [%4];" \
                 : "=r"(r0), "=r"(r1), "=r"(r2), "=r"(r3) : "r"(addr))
#define LDSM_X4_T(r0, r1, r2, r3, addr) \
    asm volatile("ldmatrix.sync.aligned.m8n8.x4.trans.shared.b16 {%0,%1,%2,%3}, [%4];" \
                 : "=r"(r0), "=r"(r1), "=r"(r2), "=r"(r3) : "r"(addr))

// m16n8k16 bf16 mma. gid=lane>>2, tig=lane&3.
// D: c0=(gid,2tig) c1=(gid,2tig+1) c2=(gid+8,2tig) c3=(gid+8,2tig+1)
__device__ __forceinline__ void mma_bf16(float& d0, float& d1, float& d2, float& d3,
                                         uint32_t a0, uint32_t a1, uint32_t a2, uint32_t a3,
                                         uint32_t b0, uint32_t b1)
{
    asm volatile("mma.sync.aligned.m16n8k16.row.col.f32.bf16.bf16.f32 "
                 "{%0,%1,%2,%3}, {%4,%5,%6,%7}, {%8,%9}, {%0,%1,%2,%3};"
                 : "+f"(d0), "+f"(d1), "+f"(d2), "+f"(d3)
                 : "r"(a0), "r"(a1), "r"(a2), "r"(a3), "r"(b0), "r"(b1));
}

// ---------------------------------------------------------------------------
// Kernel 1: QKV projection via bf16x3 mma.sync, writing hi/lo planes directly.
// out[n][o] = x^T W^T: A = x^T (n x c, trans-ldmatrix from [c][n2] smem),
// B = W^T (c x o, non-trans from [o][c2] smem). q scaled by log2e.
// Grid (18, 8), 256 threads / 8 warps; warp owns 16 n-rows.
// ---------------------------------------------------------------------------
__global__ __launch_bounds__(256, 1) void qkv_kernel(
    const float* __restrict__ x,
    const float* __restrict__ Wq, const float* __restrict__ bq,
    const float* __restrict__ Wk, const float* __restrict__ bk,
    const float* __restrict__ Wv, const float* __restrict__ bv)
{
    extern __shared__ uint32_t smu[];
    const uint32_t smb = smem_u32(smu);

    const int b    = blockIdx.y;
    const int n0   = blockIdx.x * 128;
    const int tid  = threadIdx.x;
    const int wid  = tid >> 5;
    const int lane = tid & 31;
    const int gid  = lane >> 2;
    const int tig  = lane & 3;
    const int wr   = wid * 16;
    const int rowin = lane & 7;

    // Stage x tile [c][n2] hi/lo (natural layout, vectorized).
    for (int i = tid; i < 128 * 32; i += 256) {
        int c = i >> 5, n4 = i & 31;
        float4 xv = *(const float4*)&x[((size_t)b * Cch + c) * Nn + n0 + n4 * 4];
        float h0 = rb16(xv.x), h1 = rb16(xv.y), h2 = rb16(xv.z), h3 = rb16(xv.w);
        uint2 hw = {pack_bf16(h0, h1), pack_bf16(h2, h3)};
        uint2 lw = {pack_bf16(xv.x - h0, xv.y - h1), pack_bf16(xv.z - h2, xv.w - h3)};
        *(uint2*)&smu[QKV_U_X + c * XSU + n4 * 2] = hw;
        *(uint2*)&smu[QKV_U_X + XPLANE + c * XSU + n4 * 2] = lw;
    }

    // A-frag (x^T, trans) lane address: tiles r0..r3 = (k-lo,n-lo),(k-lo,n-hi),(k-hi,n-lo),(k-hi,n-hi)
    const int laneA = (((lane >> 4) & 1) * 8 + rowin) * XSU + wr / 2 + ((lane >> 3) & 1) * 4;
    // W/B-frag (non-trans) lane address: r0..r3 = (o-lo,c-lo),(o-lo,c-hi),(o-hi,c-lo),(o-hi,c-hi)
    const int laneW = (((lane >> 4) & 1) * 8 + rowin) * WSU + ((lane >> 3) & 1) * 4;

    const float* Ws[3]   = {Wq, Wk, Wv};
    const float* bias[3] = {bq, bk, bv};
    uint32_t* outs_hi[3] = {g_qhi, g_khi, g_vhi};
    uint32_t* outs_lo[3] = {g_qlo, g_klo, g_vlo};

    for (int m = 0; m < 3; m++) {
        __syncthreads();   // xs ready / previous W readers done
        const float* W = Ws[m];
        for (int i = tid; i < 128 * 32; i += 256) {
            int o = i >> 5, c4 = i & 31;
            float4 wv = *(const float4*)&W[o * Cch + c4 * 4];
            float h0 = rb16(wv.x), h1 = rb16(wv.y), h2 = rb16(wv.z), h3 = rb16(wv.w);
            uint2 hw = {pack_bf16(h0, h1), pack_bf16(h2, h3)};
            uint2 lw = {pack_bf16(wv.x - h0, wv.y - h1), pack_bf16(wv.z - h2, wv.w - h3)};
            *(uint2*)&smu[QKV_U_W + o * WSU + c4 * 2] = hw;
            *(uint2*)&smu[QKV_U_W + XPLANE + o * WSU + c4 * 2] = lw;
        }
        __syncthreads();

        float acc[16][4];
        #pragma unroll
        for (int n = 0; n < 16; n++) {
            acc[n][0] = 0.f; acc[n][1] = 0.f; acc[n][2] = 0.f; acc[n][3] = 0.f;
        }

        #pragma unroll
        for (int kc = 0; kc < 8; kc++) {
            uint32_t ah0, ah1, ah2, ah3, al0, al1, al2, al3;
            uint32_t a_addr = smb + (QKV_U_X + kc * 16 * XSU + laneA) * 4;
            LDSM_X4_T(ah0, ah1, ah2, ah3, a_addr);
            LDSM_X4_T(al0, al1, al2, al3, a_addr + XPLANE * 4);
            #pragma unroll
            for (int np = 0; np < 8; np++) {
                uint32_t w_addr = smb + (QKV_U_W + np * 16 * WSU + kc * 8 + laneW) * 4;
                uint32_t wh0, wh1, wh2, wh3, wl0, wl1, wl2, wl3;
                LDSM_X4(wh0, wh1, wh2, wh3, w_addr);
                LDSM_X4(wl0, wl1, wl2, wl3, w_addr + XPLANE * 4);
                int na = np * 2, nb = np * 2 + 1;
                mma_bf16(acc[na][0], acc[na][1], acc[na][2], acc[na][3],
                         ah0, ah1, ah2, ah3, wh0, wh1);
                mma_bf16(acc[na][0], acc[na][1], acc[na][2], acc[na][3],
                         al0, al1, al2, al3, wh0, wh1);
                mma_bf16(acc[na][0], acc[na][1], acc[na][2], acc[na][3],
                         ah0, ah1, ah2, ah3, wl0, wl1);
                mma_bf16(acc[nb][0], acc[nb][1], acc[nb][2], acc[nb][3],
                         ah0, ah1, ah2, ah3, wh2, wh3);
                mma_bf16(acc[nb][0], acc[nb][1], acc[nb][2], acc[nb][3],
                         al0, al1, al2, al3, wh2, wh3);
                mma_bf16(acc[nb][0], acc[nb][1], acc[nb][2], acc[nb][3],
                         ah0, ah1, ah2, ah3, wl2, wl3);
            }
        }

        // Writeout hi/lo planes [b][n][c2]; q scaled by log2e (used only in S).
        const float scale = (m == 0) ? LOG2E : 1.f;
        uint32_t* ghi = outs_hi[m] + (size_t)b * Nn * 64;
        uint32_t* glo = outs_lo[m] + (size_t)b * Nn * 64;
        const int n_lo = n0 + wr + gid;
        const int n_hi = n_lo + 8;
        #pragma unroll
        for (int nch = 0; nch < 16; nch++) {
            int c0 = nch * 8 + 2 * tig;
            float b0v = bias[m][c0], b1v = bias[m][c0 + 1];
            float v0 = (acc[nch][0] + b0v) * scale;
            float v1 = (acc[nch][1] + b1v) * scale;
            float v2 = (acc[nch][2] + b0v) * scale;
            float v3 = (acc[nch][3] + b1v) * scale;
            float h0 = rb16(v0), h1 = rb16(v1), h2 = rb16(v2), h3 = rb16(v3);
            ghi[(size_t)n_lo * 64 + nch * 4 + tig] = pack_bf16(h0, h1);
            glo[(size_t)n_lo * 64 + nch * 4 + tig] = pack_bf16(v0 - h0, v1 - h1);
            ghi[(size_t)n_hi * 64 + nch * 4 + tig] = pack_bf16(h2, h3);
            glo[(size_t)n_hi * 64 + nch * 4 + tig] = pack_bf16(v2 - h2, v3 - h3);
        }
    }
}

// ---------------------------------------------------------------------------
// Kernel 2: per-(b,c) spatial mean of x.
// ---------------------------------------------------------------------------
__global__ __launch_bounds__(128) void se_mean_kernel(const float* __restrict__ x)
{
    const int bc  = blockIdx.x;
    const int tid = threadIdx.x;
    __shared__ float red[128];
    float s = 0.f;
    for (int t = tid; t < Nn; t += 128) s += x[(size_t)bc * Nn + t];
    red[tid] = s;
    __syncthreads();
    for (int off = 64; off > 0; off >>= 1) {
        if (tid < off) red[tid] += red[tid + off];
        __syncthreads();
    }
    if (tid == 0) g_mean[bc] = red[0] * (1.f / (float)Nn);
}

// ---------------------------------------------------------------------------
// Kernel 3: flash attention + fused SE-MLP prologue + fused epilogue.
// bf16x3 S (exp2 softmax) + bf16-split PV; cp.async double-buffer; ldmatrix.
// V stored [n][c2] like K; PV B-frags via ldmatrix.trans (V^T pattern).
// 256 threads / 8 warps; warp owns 16 query rows. Grid (18, 8).
// ---------------------------------------------------------------------------
__global__ __launch_bounds__(256, 1) void attn_kernel(
    const float* __restrict__ x,
    const float* __restrict__ gamma,
    const float* __restrict__ se_w1,
    const float* __restrict__ se_w2,
    float* __restrict__ out)
{
    extern __shared__ uint32_t smu[];
    const uint32_t smb = smem_u32(smu);
    float* ys = (float*)(smu + U_Y);        // y[128]
    float* hs = (float*)(smu + U_Y + 128);  // h[8]

    const int b    = blockIdx.y;
    const int m0   = blockIdx.x * BM;
    const int tid  = threadIdx.x;
    const int wid  = tid >> 5;
    const int lane = tid & 31;
    const int gid  = lane >> 2;
    const int tig  = lane & 3;
    const int wr   = wid * 16;
    const int rowin = lane & 7;

    const uint32_t* qhi = g_qhi + (size_t)b * Nn * 64;
    const uint32_t* qlo = g_qlo + (size_t)b * Nn * 64;
    const uint32_t* khi = g_khi + (size_t)b * Nn * 64;
    const uint32_t* klo = g_klo + (size_t)b * Nn * 64;
    const uint32_t* vhi = g_vhi + (size_t)b * Nn * 64;
    const uint32_t* vlo = g_vlo + (size_t)b * Nn * 64;

    // K B-frag (non-trans): tiles = (key-lo,c-lo),(key-lo,c-hi),(key-hi,c-lo),(key-hi,c-hi)
    const int laneK = (((lane >> 4) & 1) * 8 + rowin) * KSU + ((lane >> 3) & 1) * 4;
    // V B-frag (trans): tiles = (keys-lo,nch_a),(keys-hi,nch_a),(keys-lo,nch_b),(keys-hi,nch_b)
    const int laneVt = (((lane >> 3) & 1) * 8 + rowin) * KSU + (lane >> 4) * 4;
    // P A-frag (non-trans) [row][key2]
    const int laneP = (wr + ((lane >> 3) & 1) * 8 + rowin) * PSU + (lane >> 4) * 4;

    auto stage = [&](int t, int bi) {
        const int n0 = t * BN;
        #pragma unroll
        for (int ii = 0; ii < 8; ii++) {           // K planes
            int i = ii * 256 + tid;
            int plane = i >> 10, row = (i >> 4) & 63, seg = i & 15;
            uint32_t dst = smb + (U_K0 + bi * KBUF + plane * KPLANE + row * KSU + seg * 4) * 4;
            const uint32_t* src = (plane ? klo : khi) + ((size_t)(n0 + row) * 64 + seg * 4);
            CP_ASYNC16(dst, src);
        }
        #pragma unroll
        for (int ii = 0; ii < 8; ii++) {           // V planes (same structure)
            int i = ii * 256 + tid;
            int plane = i >> 10, row = (i >> 4) & 63, seg = i & 15;
            uint32_t dst = smb + (U_V0 + bi * KBUF + plane * KPLANE + row * KSU + seg * 4) * 4;
            const uint32_t* src = (plane ? vlo : vhi) + ((size_t)(n0 + row) * 64 + seg * 4);
            CP_ASYNC16(dst, src);
        }
    };

    stage(0, 0);
    CP_COMMIT();

    // Q fragments (hi/lo) from gmem, once.
    uint32_t qh[8][4], ql[8][4];
    {
        const size_t r0 = (size_t)(m0 + wr + gid) * 64;
        const size_t r1 = (size_t)(m0 + wr + gid + 8) * 64;
        #pragma unroll
        for (int kc = 0; kc < 8; kc++) {
            qh[kc][0] = qhi[r0 + kc * 8 + tig];
            qh[kc][1] = qhi[r1 + kc * 8 + tig];
            qh[kc][2] = qhi[r0 + kc * 8 + tig + 4];
            qh[kc][3] = qhi[r1 + kc * 8 + tig + 4];
            ql[kc][0] = qlo[r0 + kc * 8 + tig];
            ql[kc][1] = qlo[r1 + kc * 8 + tig];
            ql[kc][2] = qlo[r0 + kc * 8 + tig + 4];
            ql[kc][3] = qlo[r1 + kc * 8 + tig + 4];
        }
    }

    // SE-MLP prologue: h = relu(mean @ w1^T) per warp, then y = sigmoid(h @ w2^T).
    {
        float s = 0.f;
        #pragma unroll
        for (int j = 0; j < 4; j++) {
            int c = lane + j * 32;
            s += g_mean[b * Cch + c] * se_w1[wid * Cch + c];
        }
        s += __shfl_xor_sync(0xFFFFFFFF, s, 16);
        s += __shfl_xor_sync(0xFFFFFFFF, s, 8);
        s += __shfl_xor_sync(0xFFFFFFFF, s, 4);
        s += __shfl_xor_sync(0xFFFFFFFF, s, 2);
        s += __shfl_xor_sync(0xFFFFFFFF, s, 1);
        if (lane == 0) hs[wid] = fmaxf(s, 0.f);
    }
    __syncthreads();
    if (tid < 128) {
        float s = 0.f;
        #pragma unroll
        for (int r = 0; r < 8; r++) s += hs[r] * se_w2[tid * 8 + r];
        ys[tid] = 1.f / (1.f + __expf(-s));
    }

    float o_acc[16][4];
    #pragma unroll
    for (int n = 0; n < 16; n++) {
        o_acc[n][0] = 0.f; o_acc[n][1] = 0.f; o_acc[n][2] = 0.f; o_acc[n][3] = 0.f;
    }
    float l_lo = 0.f, l_hi = 0.f;

    for (int t = 0; t < NTIL; t++) {
        const int bi = t & 1;
        if (t + 1 < NTIL) {
            stage(t + 1, bi ^ 1);
            CP_COMMIT();
            CP_WAIT1();
        } else {
            CP_WAIT0();
        }
        __syncthreads();

        const uint32_t Kb = U_K0 + bi * KBUF;
        const uint32_t Vb = U_V0 + bi * KBUF;

        // ---- S = Q K^T (bf16x3) ----
        float sacc[8][4];
        #pragma unroll
        for (int n = 0; n < 8; n++) {
            sacc[n][0] = 0.f; sacc[n][1] = 0.f; sacc[n][2] = 0.f; sacc[n][3] = 0.f;
        }
        #pragma unroll
        for (int kc = 0; kc < 8; kc++) {
            #pragma unroll
            for (int np = 0; np < 4; np++) {
                uint32_t a_hi = smb + (Kb + np * (16 * KSU) + kc * 8 + laneK) * 4;
                uint32_t h0, h1, h2, h3, L0, L1, L2, L3;
                LDSM_X4(h0, h1, h2, h3, a_hi);
                LDSM_X4(L0, L1, L2, L3, a_hi + KPLANE * 4);
                int na = np * 2, nb = np * 2 + 1;
                mma_bf16(sacc[na][0], sacc[na][1], sacc[na][2], sacc[na][3],
                         qh[kc][0], qh[kc][1], qh[kc][2], qh[kc][3], h0, h1);
                mma_bf16(sacc[na][0], sacc[na][1], sacc[na][2], sacc[na][3],
                         ql[kc][0], ql[kc][1], ql[kc][2], ql[kc][3], h0, h1);
                mma_bf16(sacc[na][0], sacc[na][1], sacc[na][2], sacc[na][3],
                         qh[kc][0], qh[kc][1], qh[kc][2], qh[kc][3], L0, L1);
                mma_bf16(sacc[nb][0], sacc[nb][1], sacc[nb][2], sacc[nb][3],
                         qh[kc][0], qh[kc][1], qh[kc][2], qh[kc][3], h2, h3);
                mma_bf16(sacc[nb][0], sacc[nb][1], sacc[nb][2], sacc[nb][3],
                         ql[kc][0], ql[kc][1], ql[kc][2], ql[kc][3], h2, h3);
                mma_bf16(sacc[nb][0], sacc[nb][1], sacc[nb][2], sacc[nb][3],
                         qh[kc][0], qh[kc][1], qh[kc][2], qh[kc][3], L2, L3);
            }
        }

        // ---- p = exp2(s) (q pre-scaled by log2e) -> bf16; l sums raw p ----
        #pragma unroll
        for (int nch = 0; nch < 8; nch++) {
            float p0 = exp2f(sacc[nch][0]), p1 = exp2f(sacc[nch][1]);
            float p2 = exp2f(sacc[nch][2]), p3 = exp2f(sacc[nch][3]);
            l_lo += p0 + p1;
            l_hi += p2 + p3;
            smu[U_PS + (wr + gid)     * PSU + nch * 4 + tig] = pack_bf16(p0, p1);
            smu[U_PS + (wr + gid + 8) * PSU + nch * 4 + tig] = pack_bf16(p2, p3);
        }
        __syncwarp();

        uint32_t pf[4][4];
        #pragma unroll
        for (int kc = 0; kc < 4; kc++) {
            LDSM_X4(pf[kc][0], pf[kc][1], pf[kc][2], pf[kc][3],
                    smb + (U_PS + laneP + kc * 8) * 4);
        }

        // ---- O += P (Vhi + Vlo); V^T B-frags via ldmatrix.trans ----
        #pragma unroll
        for (int np = 0; np < 8; np++) {
            #pragma unroll
            for (int kc = 0; kc < 4; kc++) {
                uint32_t a_hi = smb + (Vb + kc * (16 * KSU) + np * 8 + laneVt) * 4;
                uint32_t h0, h1, h2, h3, L0, L1, L2, L3;
                LDSM_X4_T(h0, h1, h2, h3, a_hi);
                LDSM_X4_T(L0, L1, L2, L3, a_hi + KPLANE * 4);
                int na = np * 2, nb = np * 2 + 1;
                mma_bf16(o_acc[na][0], o_acc[na][1], o_acc[na][2], o_acc[na][3],
                         pf[kc][0], pf[kc][1], pf[kc][2], pf[kc][3], h0, h1);
                mma_bf16(o_acc[na][0], o_acc[na][1], o_acc[na][2], o_acc[na][3],
                         pf[kc][0], pf[kc][1], pf[kc][2], pf[kc][3], L0, L1);
                mma_bf16(o_acc[nb][0], o_acc[nb][1], o_acc[nb][2], o_acc[nb][3],
                         pf[kc][0], pf[kc][1], pf[kc][2], pf[kc][3], h2, h3);
                mma_bf16(o_acc[nb][0], o_acc[nb][1], o_acc[nb][2], o_acc[nb][3],
                         pf[kc][0], pf[kc][1], pf[kc][2], pf[kc][3], L2, L3);
            }
        }
        __syncthreads();
    }

    // Row sums across the quad
    l_lo += __shfl_xor_sync(0xFFFFFFFF, l_lo, 1);
    l_lo += __shfl_xor_sync(0xFFFFFFFF, l_lo, 2);
    l_hi += __shfl_xor_sync(0xFFFFFFFF, l_hi, 1);
    l_hi += __shfl_xor_sync(0xFFFFFFFF, l_hi, 2);
    const float inv_lo = 1.f / l_lo;
    const float inv_hi = 1.f / l_hi;

    // Epilogue: out[b][c][i] = gamma * O[i][c]/l[i] + x[b][c][i] * y[b][c]
    const float g = gamma[0];
    const int i_lo = m0 + wr + gid;
    const int i_hi = i_lo + 8;
    #pragma unroll
    for (int nch = 0; nch < 16; nch++) {
        int c0 = nch * 8 + 2 * tig;
        int c1 = c0 + 1;
        size_t i00 = ((size_t)b * Cch + c0) * Nn;
        size_t i01 = ((size_t)b * Cch + c1) * Nn;
        out[i00 + i_lo] = g * (o_acc[nch][0] * inv_lo) + x[i00 + i_lo] * ys[c0];
        out[i01 + i_lo] = g * (o_acc[nch][1] * inv_lo) + x[i01 + i_lo] * ys[c1];
        out[i00 + i_hi] = g * (o_acc[nch][2] * inv_hi) + x[i00 + i_hi] * ys[c0];
        out[i01 + i_hi] = g * (o_acc[nch][3] * inv_hi) + x[i01 + i_hi] * ys[c1];
    }
}

// ---------------------------------------------------------------------------
extern "C" void kernel_launch(void* const* d_in, const int* in_sizes, int n_in,
                              void* d_out, int out_size)
{
    const float* x     = (const float*)d_in[0];
    const float* Wq    = (const float*)d_in[1];
    const float* bq    = (const float*)d_in[2];
    const float* Wk    = (const float*)d_in[3];
    const float* bk    = (const float*)d_in[4];
    const float* Wv    = (const float*)d_in[5];
    const float* bv    = (const float*)d_in[6];
    const float* se_w1 = (const float*)d_in[7];
    const float* se_w2 = (const float*)d_in[8];
    const float* gamma = (const float*)d_in[9];
    float* out = (float*)d_out;

    cudaFuncSetAttribute(qkv_kernel,  cudaFuncAttributeMaxDynamicSharedMemorySize, QKV_SMEM);
    cudaFuncSetAttribute(attn_kernel, cudaFuncAttributeMaxDynamicSharedMemorySize, ATTN_SMEM);

    qkv_kernel<<<dim3(Nn / 128, Bb), 256, QKV_SMEM>>>(x, Wq, bq, Wk, bk, Wv, bv);
    se_mean_kernel<<<Bb * Cch, 128>>>(x);
    attn_kernel<<<dim3(Nn / BM, Bb), 256, ATTN_SMEM>>>(x, gamma, se_w1, se_w2, out);
}